// round 10
// baseline (speedup 1.0000x reference)
#include <cuda_runtime.h>
#include <cuda_bf16.h>
#include <cstdint>

// ---------------------------------------------------------------------------
// Problem constants
// ---------------------------------------------------------------------------
#define BATCH   8192
#define SEQ     8
#define HID     2048
#define NEXP    64
#define TOPK    8
#define ROWSTR  (SEQ * HID)

// GEMM config: BM=32, full K per CTA (256 CTAs = one wave at 2/SM),
// bf16 3-split (6 products), TWO accumulator chains (k<1024 / k>=1024)
// summed in epilogue -> bit-identical logits to the R8-passing kernel.
// 512 threads: warps 0-7 consumers (m16n16 each), warps 8-15 producers.
#define BM      32
#define KT      64                 // k-tile (f32 elements)
#define NT      (HID / KT)         // 32 tiles
#define GRID    (BATCH / BM)       // 256 CTAs

// smem plane sizes (bf16, 128B per row)
#define A_PL    4096               // 32 rows x 128B
#define B_PL    8192               // 64 rows x 128B
#define ABUF    (3 * A_PL)         // 12288
#define BBUF    (3 * B_PL)         // 24576
#define STAGE   (ABUF + BBUF)      // 36864
#define SM_ALLOC (2 * STAGE + 1024)   // 74752 -> 2 CTAs/SM

#define RS      66                 // logits smem row stride (floats)

// Scratch (no allocation allowed)
__device__ uint32_t g_bsplit[3 * NEXP * HID / 2];   // 3 bf16 planes of gate_w
__device__ float    g_bimp[GRID][NEXP];
__device__ int      g_bcnt[GRID][NEXP];
__device__ unsigned g_done;

// ---------------------------------------------------------------------------
// helpers
// ---------------------------------------------------------------------------
__device__ __forceinline__ uint32_t smem_to_u32(const void* p) {
    uint32_t a;
    asm("{ .reg .u64 t; cvta.to.shared.u64 t, %1; cvt.u32.u64 %0, t; }"
        : "=r"(a) : "l"(p));
    return a;
}
__device__ __forceinline__ void ldsm4(uint32_t* r, uint32_t addr) {
    asm volatile("ldmatrix.sync.aligned.m8n8.x4.shared.b16 {%0,%1,%2,%3}, [%4];"
                 : "=r"(r[0]), "=r"(r[1]), "=r"(r[2]), "=r"(r[3]) : "r"(addr));
}
__device__ __forceinline__ void mma16816(float* d, const uint32_t* a,
                                         const uint32_t* b) {
    asm volatile(
        "mma.sync.aligned.m16n8k16.row.col.f32.bf16.bf16.f32 "
        "{%0,%1,%2,%3}, {%4,%5,%6,%7}, {%8,%9}, {%0,%1,%2,%3};"
        : "+f"(d[0]), "+f"(d[1]), "+f"(d[2]), "+f"(d[3])
        : "r"(a[0]), "r"(a[1]), "r"(a[2]), "r"(a[3]), "r"(b[0]), "r"(b[1]));
}
__device__ __forceinline__ uint32_t pack_bf16(float lo, float hi) {
    uint32_t r;
    asm("cvt.rn.bf16x2.f32 %0, %1, %2;" : "=r"(r) : "f"(hi), "f"(lo));
    return r;
}
// fp32 -> 3x bf16 split (identical to the R8-passing kernel)
__device__ __forceinline__ void split3(float x, float y,
                                       uint32_t& h, uint32_t& m, uint32_t& l) {
    h = pack_bf16(x, y);
    float hx = __uint_as_float(h << 16);
    float hy = __uint_as_float(h & 0xffff0000u);
    float rx = x - hx, ry = y - hy;
    m = pack_bf16(rx, ry);
    float mx = __uint_as_float(m << 16);
    float my = __uint_as_float(m & 0xffff0000u);
    l = pack_bf16(rx - mx, ry - my);
}
__device__ __forceinline__ void sts64(uint32_t addr, uint32_t a, uint32_t b) {
    asm volatile("st.shared.v2.b32 [%0], {%1, %2};"
                 :: "r"(addr), "r"(a), "r"(b) : "memory");
}
__device__ __forceinline__ void sts128(uint32_t addr, uint4 v) {
    asm volatile("st.shared.v4.b32 [%0], {%1, %2, %3, %4};"
                 :: "r"(addr), "r"(v.x), "r"(v.y), "r"(v.z), "r"(v.w) : "memory");
}
// named producer/consumer barriers (512 = all threads of the CTA)
#define BAR_SYNC(id)   asm volatile("bar.sync %0, 512;"   :: "r"(id) : "memory")
#define BAR_ARRIVE(id) asm volatile("bar.arrive %0, 512;" :: "r"(id) : "memory")

__device__ __forceinline__ int redux_max_s32(int v) {
    int r;
    asm("redux.sync.max.s32 %0, %1, 0xffffffff;" : "=r"(r) : "r"(v));
    return r;
}
__device__ __forceinline__ unsigned redux_max_u32(unsigned v) {
    unsigned r;
    asm("redux.sync.max.u32 %0, %1, 0xffffffff;" : "=r"(r) : "r"(v));
    return r;
}
__device__ __forceinline__ unsigned fenc(float f) {
    int b = __float_as_int(f);
    return (unsigned)(b ^ ((b >> 31) | 0x80000000));
}
__device__ __forceinline__ float fdec(unsigned u) {
    int b = (u & 0x80000000u) ? (int)(u ^ 0x80000000u) : (int)~u;
    return __int_as_float(b);
}

// ---------------------------------------------------------------------------
// Kernel 0: pre-split gate_w into 3 bf16 planes (parallel) + reset ticket
// ---------------------------------------------------------------------------
__global__ void __launch_bounds__(256)
bsplit_kernel(const float* __restrict__ gw) {
    int p = blockIdx.x * 256 + threadIdx.x;    // 0..65535 f32-pairs
    if (p == 0) g_done = 0u;
    float2 v = ((const float2*)gw)[p];
    uint32_t h, m, l;
    split3(v.x, v.y, h, m, l);
    g_bsplit[p]             = h;
    g_bsplit[65536 + p]     = m;
    g_bsplit[2 * 65536 + p] = l;
}

// ---------------------------------------------------------------------------
// Kernel 1: fused warp-specialized HMMA GEMM (bf16 3-split, 6 products)
// + in-kernel softmax/top-8/weights/aux epilogue.
// ---------------------------------------------------------------------------
__global__ void __launch_bounds__(512, 2)
gemm_fused(const float* __restrict__ hs, float* __restrict__ out) {
    extern __shared__ char smem_raw[];
    const uint32_t base0 = smem_to_u32(smem_raw);
    const uint32_t sb    = (base0 + 1023u) & ~1023u;
    float* Ls = (float*)(smem_raw + (sb - base0));   // logits reuse stage area

    __shared__ float s_imp[16][NEXP];
    __shared__ int   s_cnt[NEXP];
    __shared__ int   s_last;
    __shared__ float s_ri[8][NEXP];
    __shared__ int   s_rc[8][NEXP];

    const int tid  = threadIdx.x;
    const int wid  = tid >> 5;
    const int lane = tid & 31;
    const int m0   = blockIdx.x * BM;

    if (tid < NEXP) s_cnt[tid] = 0;

    if (wid < 8) {
        // =================== CONSUMER (LDSM + MMA) ===================
        const int wm = (wid & 1) * 16;       // M offset within 32
        const int wn = (wid >> 1) * 16;      // N offset within 64

        uint32_t abase, amask;
        {
            int row = wm + (lane & 15);
            abase = (uint32_t)(row * 128 + (lane >> 4) * 16);
            amask = (uint32_t)((row & 7) << 4);
        }
        uint32_t bbase, bmask;
        {
            int mat = lane >> 3, r = lane & 7;
            int n  = wn + (mat >> 1) * 8 + r;
            int kb = (mat & 1) * 16;
            bbase = (uint32_t)(n * 128 + kb);
            bmask = (uint32_t)((n & 7) << 4);
        }

        float accA[2][4], accB[2][4];   // two K-chains (k<1024 / k>=1024)
#pragma unroll
        for (int h = 0; h < 2; h++)
#pragma unroll
            for (int c = 0; c < 4; c++) { accA[h][c] = 0.0f; accB[h][c] = 0.0f; }

#define GEMM_HALF(T0, ACC)                                                     \
        for (int tt = 0; tt < 16; tt++) {                                      \
            const int t = (T0) + tt;                                           \
            const int buf = t & 1;                                             \
            const uint32_t aBase = sb + (uint32_t)buf * STAGE;                 \
            const uint32_t bBase = aBase + ABUF;                               \
            BAR_SYNC(1 + buf);                                                 \
            _Pragma("unroll")                                                  \
            for (int kc = 0; kc < 4; kc++) {                                   \
                uint32_t af[3][4];                                             \
                uint32_t bf[3][4];                                             \
                _Pragma("unroll")                                              \
                for (int p = 0; p < 3; p++) {                                  \
                    ldsm4(af[p], aBase + p * A_PL + ((abase + kc * 32) ^ amask)); \
                    ldsm4(bf[p], bBase + p * B_PL + ((bbase + kc * 32) ^ bmask)); \
                }                                                              \
                const int pa[6] = {0, 0, 1, 0, 2, 1};  /* hh,hm,mh,hl,lh,mm */ \
                const int pb[6] = {0, 1, 0, 2, 0, 1};                          \
                _Pragma("unroll")                                              \
                for (int pr = 0; pr < 6; pr++) {                               \
                    mma16816(ACC[0], af[pa[pr]], &bf[pb[pr]][0]);              \
                    mma16816(ACC[1], af[pa[pr]], &bf[pb[pr]][2]);              \
                }                                                              \
            }                                                                  \
            if (t + 2 < NT) BAR_ARRIVE(3 + buf);                               \
        }

        GEMM_HALF(0,  accA)
        GEMM_HALF(16, accB)
#undef GEMM_HALF

        __syncthreads();   // all warps done with stage buffers

        // logits = chainA + chainB (same add order as R8's split-K router)
        const int r0 = wm + (lane >> 2);
        const int c0 = wn + (lane & 3) * 2;
#pragma unroll
        for (int h = 0; h < 2; h++) {
            int cc = c0 + h * 8;
            Ls[r0 * RS + cc]           = accA[h][0] + accB[h][0];
            Ls[r0 * RS + cc + 1]       = accA[h][1] + accB[h][1];
            Ls[(r0 + 8) * RS + cc]     = accA[h][2] + accB[h][2];
            Ls[(r0 + 8) * RS + cc + 1] = accA[h][3] + accB[h][3];
        }
    } else {
        // =================== PRODUCER (LDG + convert + STS) ===================
        const int wt = tid - 256;            // 0..255

        float4 ar[2], arn[2];
#define LOAD_A(t, dst) do {                                                   \
    int kk = (t) * KT;                                                        \
    _Pragma("unroll")                                                         \
    for (int i = 0; i < 2; i++) {                                             \
        int lin = wt + i * 256; int row = lin >> 4; int c4 = lin & 15;        \
        (dst)[i] = *(const float4*)(hs + (size_t)(m0 + row) * ROWSTR + kk + c4 * 4); \
    } } while (0)

        LOAD_A(0, ar);

        for (int t = 0; t < NT; t++) {
            const int buf = t & 1;
            const uint32_t aBase = sb + (uint32_t)buf * STAGE;
            const uint32_t bBase = aBase + ABUF;
            const int kk = t * KT;

            if (t + 1 < NT) LOAD_A(t + 1, arn);

            // B tile: 3 planes x 64 rows x 8 chunks(16B) = 1536 / 256 thr = 6
            uint4 bq[6];
#pragma unroll
            for (int j = 0; j < 6; j++) {
                int lin = wt + j * 256;
                int p = lin >> 9, r = (lin >> 3) & 63, ch = lin & 7;
                bq[j] = *(const uint4*)&g_bsplit[p * 65536 + r * 1024
                                                 + (kk >> 1) + ch * 4];
            }

            if (t >= 2) BAR_SYNC(3 + buf);   // wait tile free

            // convert + swizzled store: A (3 planes, identical split3 values)
#pragma unroll
            for (int i = 0; i < 2; i++) {
                int lin = wt + i * 256; int row = lin >> 4; int c4 = lin & 15;
                uint32_t off = (uint32_t)(row * 128 + c4 * 8);
                uint32_t sw  = off ^ ((off >> 3) & 0x70u);
                uint32_t h0, mm0, l0, h1, mm1, l1;
                split3(ar[i].x, ar[i].y, h0, mm0, l0);
                split3(ar[i].z, ar[i].w, h1, mm1, l1);
                sts64(aBase + sw,            h0,  h1);
                sts64(aBase + A_PL + sw,     mm0, mm1);
                sts64(aBase + 2 * A_PL + sw, l0,  l1);
            }
            // store pre-split B (16B chunks; swizzle constant per chunk)
#pragma unroll
            for (int j = 0; j < 6; j++) {
                int lin = wt + j * 256;
                int p = lin >> 9, r = (lin >> 3) & 63, ch = lin & 7;
                uint32_t off = (uint32_t)(r * 128 + ch * 16);
                uint32_t sw  = off ^ ((off >> 3) & 0x70u);
                sts128(bBase + p * B_PL + sw, bq[j]);
            }
            BAR_ARRIVE(1 + buf);             // tile full

#pragma unroll
            for (int i = 0; i < 2; i++) ar[i] = arn[i];
        }
#undef LOAD_A
        __syncthreads();   // match consumers
    }

    __syncthreads();       // logits visible to all warps

    // ============ fused router: 16 warps x 2 rows each ============
    const int w = wid;
    float imp0 = 0.0f, imp1 = 0.0f;
#pragma unroll
    for (int rr = 0; rr < 2; rr++) {
        const int lrow = w * 2 + rr;
        const int grow = m0 + lrow;
        float l0 = Ls[lrow * RS + lane];
        float l1 = Ls[lrow * RS + lane + 32];

        unsigned em = redux_max_u32(fenc(fmaxf(l0, l1)));
        float m = fdec(em);
        float p0 = __expf(l0 - m);
        float p1 = __expf(l1 - m);
        float sm = p0 + p1;
#pragma unroll
        for (int off = 16; off; off >>= 1)
            sm += __shfl_xor_sync(0xffffffffu, sm, off);
        float inv = 1.0f / sm;
        p0 *= inv;
        p1 *= inv;
        imp0 += p0;
        imp1 += p1;

        const int NEG1 = 0xBF800000;
        int b0i = __float_as_int(p0);
        int b1i = __float_as_int(p1);
        bool sel0 = false, sel1 = false;
        float wsum = 0.0f, myv = 0.0f;
        int myi = 0;
#pragma unroll
        for (int it = 0; it < TOPK; it++) {
            int c0 = sel0 ? NEG1 : b0i;
            int c1 = sel1 ? NEG1 : b1i;
            int mv = redux_max_s32(c0 > c1 ? c0 : c1);
            unsigned q0 = __ballot_sync(0xffffffffu, c0 == mv);
            unsigned q1 = __ballot_sync(0xffffffffu, c1 == mv);
            int idx = q0 ? (__ffs(q0) - 1) : (__ffs(q1) + 31);
            float fv = __int_as_float(mv);
            wsum += fv;
            if (idx == lane)           sel0 = true;
            else if (idx == lane + 32) sel1 = true;
            if (lane == it) { myv = fv; myi = idx; }
            if (lane == 0)  atomicAdd(&s_cnt[idx], 1);
        }

        float invw = 1.0f / fmaxf(wsum, 1e-8f);
        if (lane < TOPK) {
            out[(size_t)grow * TOPK + lane] = (float)myi;
            out[(size_t)BATCH * TOPK + (size_t)grow * TOPK + lane] = myv * invw;
        }
    }

    s_imp[w][lane]      = imp0;
    s_imp[w][lane + 32] = imp1;
    __syncthreads();

    // per-CTA partials -> private global slots
    if (tid < NEXP) {
        float si = 0.0f;
#pragma unroll
        for (int ww = 0; ww < 16; ww++) si += s_imp[ww][tid];
        g_bimp[blockIdx.x][tid] = si;
        g_bcnt[blockIdx.x][tid] = s_cnt[tid];
        __threadfence();
    }
    __syncthreads();
    if (tid == 0) {
        unsigned tk = atomicAdd(&g_done, 1u);
        s_last = (tk == gridDim.x - 1) ? 1 : 0;
    }
    __syncthreads();

    if (s_last) {
        // parallel tail: 512 threads = 8 chunks x 64 experts, 32 blocks each
        const int e  = tid & 63;
        const int ch = tid >> 6;
        float si = 0.0f;
        int   sc = 0;
#pragma unroll
        for (int b = ch * 32; b < ch * 32 + 32; b++) {
            si += *(volatile float*)&g_bimp[b][e];
            sc += *(volatile int*)&g_bcnt[b][e];
        }
        s_ri[ch][e] = si;
        s_rc[ch][e] = sc;
        __syncthreads();
        if (tid < NEXP) {
            float ti = 0.0f;
            int   tc = 0;
#pragma unroll
            for (int c = 0; c < 8; c++) { ti += s_ri[c][tid]; tc += s_rc[c][tid]; }
            s_ri[0][tid] = (float)NEXP * (ti / (float)BATCH) *
                           ((float)tc / (float)(BATCH * TOPK));
        }
        __syncthreads();
        if (tid == 0) {
            float s = 0.0f;
#pragma unroll
            for (int i = 0; i < NEXP; i++) s += s_ri[0][i];
            out[(size_t)2 * BATCH * TOPK] = s;
        }
    }
}

// ---------------------------------------------------------------------------
extern "C" void kernel_launch(void* const* d_in, const int* in_sizes, int n_in,
                              void* d_out, int out_size) {
    const float* hs  = (const float*)d_in[0];
    const float* gw  = (const float*)d_in[1];
    float*       out = (float*)d_out;

    cudaFuncSetAttribute(gemm_fused, cudaFuncAttributeMaxDynamicSharedMemorySize,
                         SM_ALLOC);
    bsplit_kernel<<<256, 256>>>(gw);
    gemm_fused<<<GRID, 512, SM_ALLOC>>>(hs, out);
}

// round 11
// speedup vs baseline: 1.2099x; 1.2099x over previous
#include <cuda_runtime.h>
#include <cuda_bf16.h>
#include <cstdint>

// ---------------------------------------------------------------------------
// Problem constants
// ---------------------------------------------------------------------------
#define BATCH   8192
#define SEQ     8
#define HID     2048
#define NEXP    64
#define TOPK    8
#define ROWSTR  (SEQ * HID)

// GEMM config: BM=64, split-K=2 (256 CTAs, one wave at 2/SM).
// Warps 0-3: consumers (m32n32, LDSM A + direct-LDG B frags + MMA).
// Warps 4-7: producers (LDG A f32 -> split3 -> STS). B never touches smem.
#define BM      64
#define KT      64                 // k-tile (f32 elements)
#define KSPL    2
#define KHALF   (HID / KSPL)       // 1024
#define NT      (KHALF / KT)       // 16 tiles per split

// smem: A only now (bf16, 128B per row), double buffered
#define A_PL    8192               // 64 rows x 128B
#define ABUF    (3 * A_PL)         // 24576
#define STAGE   ABUF
#define SM_ALLOC (2 * STAGE + 1024)   // 50176 -> 2 CTAs/SM

// B fragment store: [plane(3)][n8 group(8)][k16 chunk(128)][lane(32)][2 u32]
#define NCH     (HID / 16)         // 128 k16 chunks

// Router config
#define RBLK    512
#define RTHR    512
#define RWARPS  (RTHR / 32)        // 16

// Scratch (no allocation allowed)
__device__ float    g_partial[KSPL][BATCH * NEXP];  // 4 MB
__device__ uint32_t g_bfrag[3 * 8 * NCH * 64];      // 768 KB, frag-ordered B
__device__ float    g_bimp[RBLK][NEXP];
__device__ int      g_bcnt[RBLK][NEXP];
__device__ unsigned g_done;

// ---------------------------------------------------------------------------
// helpers
// ---------------------------------------------------------------------------
__device__ __forceinline__ uint32_t smem_to_u32(const void* p) {
    uint32_t a;
    asm("{ .reg .u64 t; cvta.to.shared.u64 t, %1; cvt.u32.u64 %0, t; }"
        : "=r"(a) : "l"(p));
    return a;
}
__device__ __forceinline__ void ldsm4(uint32_t* r, uint32_t addr) {
    asm volatile("ldmatrix.sync.aligned.m8n8.x4.shared.b16 {%0,%1,%2,%3}, [%4];"
                 : "=r"(r[0]), "=r"(r[1]), "=r"(r[2]), "=r"(r[3]) : "r"(addr));
}
__device__ __forceinline__ void mma16816(float* d, const uint32_t* a,
                                         const uint32_t* b) {
    asm volatile(
        "mma.sync.aligned.m16n8k16.row.col.f32.bf16.bf16.f32 "
        "{%0,%1,%2,%3}, {%4,%5,%6,%7}, {%8,%9}, {%0,%1,%2,%3};"
        : "+f"(d[0]), "+f"(d[1]), "+f"(d[2]), "+f"(d[3])
        : "r"(a[0]), "r"(a[1]), "r"(a[2]), "r"(a[3]), "r"(b[0]), "r"(b[1]));
}
__device__ __forceinline__ uint32_t pack_bf16(float lo, float hi) {
    uint32_t r;
    asm("cvt.rn.bf16x2.f32 %0, %1, %2;" : "=r"(r) : "f"(hi), "f"(lo));
    return r;
}
// fp32 -> 3x bf16 split (byte-identical to the R8-passing kernel)
__device__ __forceinline__ void split3(float x, float y,
                                       uint32_t& h, uint32_t& m, uint32_t& l) {
    h = pack_bf16(x, y);
    float hx = __uint_as_float(h << 16);
    float hy = __uint_as_float(h & 0xffff0000u);
    float rx = x - hx, ry = y - hy;
    m = pack_bf16(rx, ry);
    float mx = __uint_as_float(m << 16);
    float my = __uint_as_float(m & 0xffff0000u);
    l = pack_bf16(rx - mx, ry - my);
}
__device__ __forceinline__ void sts64(uint32_t addr, uint32_t a, uint32_t b) {
    asm volatile("st.shared.v2.b32 [%0], {%1, %2};"
                 :: "r"(addr), "r"(a), "r"(b) : "memory");
}
// named producer/consumer barriers (256 = all threads of the CTA)
#define BAR_SYNC(id)   asm volatile("bar.sync %0, 256;"   :: "r"(id) : "memory")
#define BAR_ARRIVE(id) asm volatile("bar.arrive %0, 256;" :: "r"(id) : "memory")

__device__ __forceinline__ int redux_max_s32(int v) {
    int r;
    asm("redux.sync.max.s32 %0, %1, 0xffffffff;" : "=r"(r) : "r"(v));
    return r;
}
__device__ __forceinline__ unsigned redux_max_u32(unsigned v) {
    unsigned r;
    asm("redux.sync.max.u32 %0, %1, 0xffffffff;" : "=r"(r) : "r"(v));
    return r;
}
__device__ __forceinline__ unsigned fenc(float f) {
    int b = __float_as_int(f);
    return (unsigned)(b ^ ((b >> 31) | 0x80000000));
}
__device__ __forceinline__ float fdec(unsigned u) {
    int b = (u & 0x80000000u) ? (int)(u ^ 0x80000000u) : (int)~u;
    return __int_as_float(b);
}

// ---------------------------------------------------------------------------
// Kernel 0: split gate_w into 3 bf16 planes laid out in MMA FRAGMENT order.
// Fragment (p, g, c): lane t holds {b0, b1} where
//   b0 = pack(B[n = g*8 + t/4][k = c*16 + (t%4)*2], k+1)
//   b1 = same with k += 8
// matching ldmatrix.x4 output regs 0/1 (and 2/3 for the next n8 group).
// ---------------------------------------------------------------------------
__global__ void __launch_bounds__(256)
bsplit_kernel(const float* __restrict__ gw) {
    int id = blockIdx.x * 256 + threadIdx.x;   // 0..32767
    if (id == 0) g_done = 0u;
    int t = id & 31;
    int c = (id >> 5) & 127;
    int g = id >> 12;                          // 0..7
    int n  = g * 8 + (t >> 2);
    int k0 = c * 16 + (t & 3) * 2;

    float2 v0 = *(const float2*)(gw + (size_t)n * HID + k0);
    float2 v1 = *(const float2*)(gw + (size_t)n * HID + k0 + 8);
    uint32_t h0, m0, l0, h1, m1, l1;
    split3(v0.x, v0.y, h0, m0, l0);
    split3(v1.x, v1.y, h1, m1, l1);

    int fi = (g * NCH + c) * 64 + t * 2;       // within-plane u32 index
    const int PL = 8 * NCH * 64;               // plane stride in u32
    *(uint2*)&g_bfrag[fi]          = make_uint2(h0, h1);
    *(uint2*)&g_bfrag[PL + fi]     = make_uint2(m0, m1);
    *(uint2*)&g_bfrag[2 * PL + fi] = make_uint2(l0, l1);
}

// ---------------------------------------------------------------------------
// Kernel 1: HMMA logits GEMM, bf16 3-split (6 products), B via direct LDG.
// ---------------------------------------------------------------------------
__global__ void __launch_bounds__(256, 2)
gemm_tc(const float* __restrict__ hs) {
    extern __shared__ char smem_raw[];
    const uint32_t sb = (smem_to_u32(smem_raw) + 1023u) & ~1023u;

    const int tid  = threadIdx.x;
    const int wid  = tid >> 5;
    const int lane = tid & 31;
    const int m0   = blockIdx.x * BM;
    const int sp   = blockIdx.y;
    const int k0   = sp * KHALF;

    if (wid < 4) {
        // =================== CONSUMER ===================
        const int wm = (wid & 1) * 32;
        const int wn = (wid >> 1) * 32;
        const int gbase = wn >> 3;             // first n8 group (0 or 4)

        uint32_t abase[2], amask[2];
#pragma unroll
        for (int mt = 0; mt < 2; mt++) {
            int row = wm + mt * 16 + (lane & 15);
            abase[mt] = (uint32_t)(row * 128 + (lane >> 4) * 16);
            amask[mt] = (uint32_t)((row & 7) << 4);
        }

        float acc[2][4][4];                    // [mt][n8 group j][4]
#pragma unroll
        for (int a = 0; a < 2; a++)
#pragma unroll
            for (int b = 0; b < 4; b++)
#pragma unroll
                for (int c = 0; c < 4; c++) acc[a][b][c] = 0.0f;

        const int pa[6] = {0, 0, 1, 0, 2, 1};  // hh, hm, mh, hl, lh, mm
        const int pb[6] = {0, 1, 0, 2, 0, 1};

        const int PL = 8 * NCH * 64;           // plane stride (u32)
        const int csp = sp * (KHALF / 16);     // first chunk of this split

        // B frag double buffer in registers (one kc ahead)
        uint2 bb0[3][4], bb1[3][4];
#define LOAD_B(dst, cc) do {                                                  \
    _Pragma("unroll")                                                         \
    for (int p = 0; p < 3; p++) {                                             \
        _Pragma("unroll")                                                     \
        for (int j = 0; j < 4; j++)                                           \
            (dst)[p][j] = __ldg((const uint2*)&g_bfrag[                       \
                p * PL + ((gbase + j) * NCH + (csp + (cc))) * 64] + lane);    \
    } } while (0)

        LOAD_B(bb0, 0);

        for (int t = 0; t < NT; t++) {
            const int buf = t & 1;
            const uint32_t aBase = sb + (uint32_t)buf * STAGE;

            BAR_SYNC(1 + buf);          // wait A tile full

#pragma unroll
            for (int kc = 0; kc < 4; kc++) {
                uint32_t af[3][2][4];
#pragma unroll
                for (int p = 0; p < 3; p++)
#pragma unroll
                    for (int mt = 0; mt < 2; mt++)
                        ldsm4(af[p][mt],
                              aBase + p * A_PL + ((abase[mt] + kc * 32) ^ amask[mt]));

                // prefetch next kc's B frags into the other buffer
                if (kc < 3) {
                    if (kc & 1) { LOAD_B(bb0, t * 4 + kc + 1); }
                    else        { LOAD_B(bb1, t * 4 + kc + 1); }
                } else if (t + 1 < NT) {
                    LOAD_B(bb0, t * 4 + 4);   // kc=3 is odd -> next goes to bb0
                }

#pragma unroll
                for (int pr = 0; pr < 6; pr++) {
#pragma unroll
                    for (int mt = 0; mt < 2; mt++) {
#pragma unroll
                        for (int j = 0; j < 4; j++) {
                            const uint2* bf = (kc & 1) ? &bb1[pb[pr]][j]
                                                       : &bb0[pb[pr]][j];
                            mma16816(acc[mt][j], af[pa[pr]][mt],
                                     (const uint32_t*)bf);
                        }
                    }
                }
            }
            if (t + 2 < NT) BAR_ARRIVE(3 + buf);   // A tile free
        }
#undef LOAD_B

        // epilogue: warp writes its 32x32 f32 tile to split partials
        const int gr = m0 + wm + (lane >> 2);
        const int gc = wn + (lane & 3) * 2;
#pragma unroll
        for (int mt = 0; mt < 2; mt++) {
#pragma unroll
            for (int j = 0; j < 4; j++) {
                int row = gr + mt * 16;
                int col = gc + j * 8;
                *(float2*)&g_partial[sp][(size_t)row * NEXP + col] =
                    make_float2(acc[mt][j][0], acc[mt][j][1]);
                *(float2*)&g_partial[sp][(size_t)(row + 8) * NEXP + col] =
                    make_float2(acc[mt][j][2], acc[mt][j][3]);
            }
        }
    } else {
        // =================== PRODUCER (A only) ===================
        const int wt = tid & 127;     // 0..127

        float4 ar[8], arn[8];
#define LOAD_A(t, dst) do {                                                   \
    int kk = k0 + (t) * KT;                                                   \
    _Pragma("unroll")                                                         \
    for (int i = 0; i < 8; i++) {                                             \
        int lin = wt + i * 128; int row = lin >> 4; int c4 = lin & 15;        \
        (dst)[i] = *(const float4*)(hs + (size_t)(m0 + row) * ROWSTR + kk + c4 * 4); \
    } } while (0)

        LOAD_A(0, ar);

        for (int t = 0; t < NT; t++) {
            const int buf = t & 1;
            const uint32_t aBase = sb + (uint32_t)buf * STAGE;

            if (t + 1 < NT) LOAD_A(t + 1, arn);
            if (t >= 2) BAR_SYNC(3 + buf);   // wait tile free

            // convert + swizzled store: A (3 planes, identical split3 values)
#pragma unroll
            for (int i = 0; i < 8; i++) {
                int lin = wt + i * 128; int row = lin >> 4; int c4 = lin & 15;
                uint32_t off = (uint32_t)(row * 128 + c4 * 8);
                uint32_t sw  = off ^ ((off >> 3) & 0x70u);
                uint32_t h0, mm0, l0, h1, mm1, l1;
                split3(ar[i].x, ar[i].y, h0, mm0, l0);
                split3(ar[i].z, ar[i].w, h1, mm1, l1);
                sts64(aBase + sw,            h0,  h1);
                sts64(aBase + A_PL + sw,     mm0, mm1);
                sts64(aBase + 2 * A_PL + sw, l0,  l1);
            }
            BAR_ARRIVE(1 + buf);             // tile full

#pragma unroll
            for (int i = 0; i < 8; i++) ar[i] = arn[i];
        }
#undef LOAD_A
    }
}

// ---------------------------------------------------------------------------
// Kernel 2: warp-per-row softmax + top-8 (redux argmax) + weights + aux.
// ---------------------------------------------------------------------------
__global__ void __launch_bounds__(RTHR)
router_kernel(float* __restrict__ out) {
    __shared__ float s_pr[RWARPS][NEXP];
    __shared__ int   s_cnt[NEXP];
    __shared__ int   s_last;
    const int tid  = threadIdx.x;
    const int lane = tid & 31;
    const int w    = tid >> 5;
    if (tid < NEXP) s_cnt[tid] = 0;
    __syncthreads();

    const int row = blockIdx.x * RWARPS + w;

    const float* p0p = &g_partial[0][(size_t)row * NEXP];
    const float* p1p = &g_partial[1][(size_t)row * NEXP];
    float l0 = p0p[lane] + p1p[lane];
    float l1 = p0p[lane + 32] + p1p[lane + 32];

    unsigned em = redux_max_u32(fenc(fmaxf(l0, l1)));
    float m = fdec(em);
    float p0 = __expf(l0 - m);
    float p1 = __expf(l1 - m);
    float sm = p0 + p1;
#pragma unroll
    for (int off = 16; off; off >>= 1)
        sm += __shfl_xor_sync(0xffffffffu, sm, off);
    float inv = 1.0f / sm;
    p0 *= inv;
    p1 *= inv;

    s_pr[w][lane]      = p0;
    s_pr[w][lane + 32] = p1;

    const int NEG1 = 0xBF800000;
    int b0i = __float_as_int(p0);
    int b1i = __float_as_int(p1);
    bool sel0 = false, sel1 = false;
    float wsum = 0.0f, myv = 0.0f;
    int myi = 0;
#pragma unroll
    for (int it = 0; it < TOPK; it++) {
        int c0 = sel0 ? NEG1 : b0i;
        int c1 = sel1 ? NEG1 : b1i;
        int mv = redux_max_s32(c0 > c1 ? c0 : c1);
        unsigned q0 = __ballot_sync(0xffffffffu, c0 == mv);
        unsigned q1 = __ballot_sync(0xffffffffu, c1 == mv);
        int idx = q0 ? (__ffs(q0) - 1) : (__ffs(q1) + 31);
        float fv = __int_as_float(mv);
        wsum += fv;
        if (idx == lane)           sel0 = true;
        else if (idx == lane + 32) sel1 = true;
        if (lane == it) { myv = fv; myi = idx; }
        if (lane == 0)  atomicAdd(&s_cnt[idx], 1);
    }

    float invw = 1.0f / fmaxf(wsum, 1e-8f);
    if (lane < TOPK) {
        out[(size_t)row * TOPK + lane] = (float)myi;
        out[(size_t)BATCH * TOPK + (size_t)row * TOPK + lane] = myv * invw;
    }

    __syncthreads();

    if (tid < NEXP) {
        float si = 0.0f;
#pragma unroll
        for (int ww = 0; ww < RWARPS; ww++) si += s_pr[ww][tid];
        g_bimp[blockIdx.x][tid] = si;
        g_bcnt[blockIdx.x][tid] = s_cnt[tid];
        __threadfence();
    }
    __syncthreads();
    if (tid == 0) {
        unsigned tk = atomicAdd(&g_done, 1u);
        s_last = (tk == gridDim.x - 1) ? 1 : 0;
    }
    __syncthreads();

    if (s_last) {
        __shared__ float s_ri[8][NEXP];
        __shared__ int   s_rc[8][NEXP];
        const int e  = tid & 63;
        const int ch = tid >> 6;
        float si = 0.0f;
        int   sc = 0;
#pragma unroll 8
        for (int b = ch * (RBLK / 8); b < (ch + 1) * (RBLK / 8); b++) {
            si += *(volatile float*)&g_bimp[b][e];
            sc += *(volatile int*)&g_bcnt[b][e];
        }
        s_ri[ch][e] = si;
        s_rc[ch][e] = sc;
        __syncthreads();
        if (tid < NEXP) {
            float ti = 0.0f;
            int   tc = 0;
#pragma unroll
            for (int c = 0; c < 8; c++) { ti += s_ri[c][tid]; tc += s_rc[c][tid]; }
            s_ri[0][tid] = (float)NEXP * (ti / (float)BATCH) *
                           ((float)tc / (float)(BATCH * TOPK));
        }
        __syncthreads();
        if (tid == 0) {
            float s = 0.0f;
#pragma unroll
            for (int i = 0; i < NEXP; i++) s += s_ri[0][i];
            out[(size_t)2 * BATCH * TOPK] = s;
        }
    }
}

// ---------------------------------------------------------------------------
extern "C" void kernel_launch(void* const* d_in, const int* in_sizes, int n_in,
                              void* d_out, int out_size) {
    const float* hs  = (const float*)d_in[0];
    const float* gw  = (const float*)d_in[1];
    float*       out = (float*)d_out;

    cudaFuncSetAttribute(gemm_tc, cudaFuncAttributeMaxDynamicSharedMemorySize,
                         SM_ALLOC);
    bsplit_kernel<<<128, 256>>>(gw);
    gemm_tc<<<dim3(BATCH / BM, KSPL), 256, SM_ALLOC>>>(hs);
    router_kernel<<<RBLK, RTHR>>>(out);
}